// round 12
// baseline (speedup 1.0000x reference)
#include <cuda_runtime.h>

#define NB  4
#define NPT 16384
#define NQ  1024
#define KK  20
#define KK1 21
#define NCELL 4096

// output layout (all f32, concatenated in reference return order)
#define OFF_IND 0
#define OFF_Q   (NB*NQ)                   // 4096
#define OFF_NM  (OFF_Q  + NB*NQ*3)        // 16384
#define OFF_DM  (OFF_NM + NB*NQ*KK)       // 98304
#define OFF_NO  (OFF_DM + NB*NQ*KK*3)     // 344064
#define OFF_DO  (OFF_NO + NB*NQ*KK)       // 425984

__device__ float4   g_query4[NB*NQ];    // sampled queries (x,y,z,|q|^2)
__device__ float4   g_pts4[NB*NPT];     // packed points  (x,y,z,|p|^2)
__device__ unsigned g_sidx[NB*NPT];     // sorted-pos -> original index

// ---------------- packed f32x2 helpers (per-half IEEE RN, exact) ----------
__device__ __forceinline__ unsigned long long pack2(float a, float b)
{ unsigned long long r; asm("mov.b64 %0, {%1, %2};" : "=l"(r) : "f"(a), "f"(b)); return r; }
__device__ __forceinline__ void unpack2(unsigned long long v, float& a, float& b)
{ asm("mov.b64 {%0, %1}, %2;" : "=f"(a), "=f"(b) : "l"(v)); }
__device__ __forceinline__ unsigned long long add2(unsigned long long a, unsigned long long b)
{ unsigned long long r; asm("add.rn.f32x2 %0, %1, %2;" : "=l"(r) : "l"(a), "l"(b)); return r; }
__device__ __forceinline__ unsigned long long mul2(unsigned long long a, unsigned long long b)
{ unsigned long long r; asm("mul.rn.f32x2 %0, %1, %2;" : "=l"(r) : "l"(a), "l"(b)); return r; }

__device__ __forceinline__ unsigned morton4(unsigned cx, unsigned cy, unsigned cz)
{
    unsigned m = 0;
#pragma unroll
    for (int b = 0; b < 4; ++b)
        m |= (((cx >> b) & 1u) << (3 * b))
           | (((cy >> b) & 1u) << (3 * b + 1))
           | (((cz >> b) & 1u) << (3 * b + 2));
    return m;
}

__device__ __forceinline__ unsigned cellof(float x, float y, float z)
{
    unsigned cx = (unsigned)fminf(fmaxf((x + 4.0f) * 2.0f, 0.0f), 15.0f);
    unsigned cy = (unsigned)fminf(fmaxf((y + 4.0f) * 2.0f, 0.0f), 15.0f);
    unsigned cz = (unsigned)fminf(fmaxf((z + 4.0f) * 2.0f, 0.0f), 15.0f);
    return morton4(cx, cy, cz);
}

// ---------------------------------------------------------------------------
// pack points into float4 (x,y,z,|p|^2); sq uses the exact reference op
// sequence so every later use is bit-identical.
// ---------------------------------------------------------------------------
__global__ __launch_bounds__(256)
void pack_kernel(const float* __restrict__ pts)
{
    int i = blockIdx.x * 256 + threadIdx.x;      // 0 .. NB*NPT-1
    float x = pts[i * 3], y = pts[i * 3 + 1], z = pts[i * 3 + 2];
    float sq = __fadd_rn(__fadd_rn(__fmul_rn(x, x), __fmul_rn(y, y)),
                         __fmul_rn(z, z));
    g_pts4[i] = make_float4(x, y, z, sq);
}

// ---------------------------------------------------------------------------
// Bucketed FPS, one CTA per batch, 1024 threads x 16-pt buckets.
// R10 config + ONE new mechanism: warp-level skip. Each warp keeps its
// union bbox (registers) and its cached stage-1 result (wd,wi). If the
// warp bbox lower bound can't beat wd, no thread can improve and the warp's
// contribution is unchanged -> lane0 re-stores (wd,wi), skipping thread
// bbox eval, scan, resolve and both redux. Exact: bm only decreases; (wd,wi)
// recomputed whenever the warp takes the active path.
// Distance = plain non-contracted left-to-right sum of squares via packed
// f32x2 (per-half IEEE RN, bit-identical to scalar). Tie-break = reference
// argmax first index (max inv = 0xFFFF^idx).
// ---------------------------------------------------------------------------
__global__ __launch_bounds__(1024, 1)
void fps_kernel(const float* __restrict__ pts, float* __restrict__ out)
{
    extern __shared__ float sm[];
    float*    sxf  = sm;                       // pair layout, see scatter
    float*    syf  = sm + NPT;
    float*    szf  = sm + 2 * NPT;
    unsigned* hist = (unsigned*)(sm + 3 * NPT);   // 16KB, sort phase only
    const unsigned long long* sxq = (const unsigned long long*)sxf;
    const unsigned long long* syq = (const unsigned long long*)syf;
    const unsigned long long* szq = (const unsigned long long*)szf;

    __shared__ unsigned long long s_part[2][32];
    __shared__ unsigned s_wsum[32];

    const int b    = blockIdx.x;
    const int tid  = threadIdx.x;
    const int lane = tid & 31, wid = tid >> 5;
    const float* P = pts + (size_t)b * NPT * 3;
    unsigned* sidx = g_sidx + b * NPT;

    // ---- counting sort by Morton cell ----
#pragma unroll
    for (int k = 0; k < 4; ++k) hist[tid + k * 1024] = 0;
    __syncthreads();

#pragma unroll
    for (int k = 0; k < 16; ++k) {
        int i = tid + k * 1024;
        float x = P[i * 3], y = P[i * 3 + 1], z = P[i * 3 + 2];
        atomicAdd(&hist[cellof(x, y, z)], 1u);
    }
    __syncthreads();

    // exclusive scan of hist[4096] in place
    unsigned v0 = hist[4 * tid], v1 = hist[4 * tid + 1];
    unsigned v2 = hist[4 * tid + 2], v3 = hist[4 * tid + 3];
    unsigned s = v0 + v1 + v2 + v3;
    unsigned inc = s;
#pragma unroll
    for (int o = 1; o < 32; o <<= 1) {
        unsigned n = __shfl_up_sync(0xffffffffu, inc, o);
        if (lane >= o) inc += n;
    }
    if (lane == 31) s_wsum[wid] = inc;
    __syncthreads();
    if (tid < 32) {
        unsigned w = s_wsum[tid], wi2 = w;
#pragma unroll
        for (int o = 1; o < 32; o <<= 1) {
            unsigned n = __shfl_up_sync(0xffffffffu, wi2, o);
            if (tid >= o) wi2 += n;
        }
        s_wsum[tid] = wi2 - w;   // exclusive warp base
    }
    __syncthreads();
    unsigned base = s_wsum[wid] + inc - s;
    hist[4 * tid]     = base;
    hist[4 * tid + 1] = base + v0;
    hist[4 * tid + 2] = base + v0 + v1;
    hist[4 * tid + 3] = base + v0 + v1 + v2;
    __syncthreads();

    // scatter: sorted pos p (bucket t=p>>4, j=p&15) -> pair-layout float slot
    //   fs = (j>>1)*2048 + (t<<1) + (j&1)   (conflict-free LDS.64 per warp)
#pragma unroll
    for (int k = 0; k < 16; ++k) {
        int i = tid + k * 1024;
        float x = P[i * 3], y = P[i * 3 + 1], z = P[i * 3 + 2];
        unsigned pos = atomicAdd(&hist[cellof(x, y, z)], 1u);
        int t = (int)(pos >> 4), j = (int)(pos & 15u);
        int fs = (j >> 1) * 2048 + (t << 1) + (j & 1);
        sxf[fs] = x; syf[fs] = y; szf[fs] = z;
        sidx[pos] = (unsigned)i;
    }
    __syncthreads();

    // ---- per-bucket state ----
    float    mind[16];
    unsigned pk[8];
    float lox = 1e30f, loy = 1e30f, loz = 1e30f;
    float hix = -1e30f, hiy = -1e30f, hiz = -1e30f;
#pragma unroll
    for (int j = 0; j < 16; ++j) {
        int fs = (j >> 1) * 2048 + (tid << 1) + (j & 1);
        float x = sxf[fs], y = syf[fs], z = szf[fs];
        lox = fminf(lox, x); hix = fmaxf(hix, x);
        loy = fminf(loy, y); hiy = fmaxf(hiy, y);
        loz = fminf(loz, z); hiz = fmaxf(hiz, z);
        mind[j] = 1e10f;
        unsigned inv = 0xFFFFu ^ sidx[16 * tid + j];
        if (j & 1) pk[j >> 1] |= inv << 16;
        else       pk[j >> 1]  = inv;
    }
    float bm = 1e10f;
    unsigned bpk = 0;
#pragma unroll
    for (int j = 0; j < 16; ++j) {
        unsigned inv = (j & 1) ? (pk[j >> 1] >> 16) : (pk[j >> 1] & 0xFFFFu);
        unsigned val = (inv << 16) |
            (unsigned)((j >> 1) * 2048 + (tid << 1) + (j & 1));
        bpk = val > bpk ? val : bpk;    // all mind equal -> max inv
    }

    // warp union bbox (separate registers; thread bbox kept)
    float wlox = lox, wloy = loy, wloz = loz;
    float whix = hix, whiy = hiy, whiz = hiz;
#pragma unroll
    for (int o = 16; o; o >>= 1) {
        wlox = fminf(wlox, __shfl_xor_sync(0xffffffffu, wlox, o));
        wloy = fminf(wloy, __shfl_xor_sync(0xffffffffu, wloy, o));
        wloz = fminf(wloz, __shfl_xor_sync(0xffffffffu, wloz, o));
        whix = fmaxf(whix, __shfl_xor_sync(0xffffffffu, whix, o));
        whiy = fmaxf(whiy, __shfl_xor_sync(0xffffffffu, whiy, o));
        whiz = fmaxf(whiz, __shfl_xor_sync(0xffffffffu, whiz, o));
    }
    unsigned wd = __float_as_uint(1e10f);             // cached warp dmax bits
    unsigned wi = __reduce_max_sync(0xffffffffu, bpk); // cached warp imax

    // first sample = original index 0 (broadcast LDG)
    float qx = P[0], qy = P[1], qz = P[2];
    if (tid == 0) {
        out[OFF_IND + b * NQ] = 0.0f;
        float* oq = out + OFF_Q + (size_t)b * NQ * 3;
        oq[0] = qx; oq[1] = qy; oq[2] = qz;
        float sq = __fadd_rn(__fadd_rn(__fmul_rn(qx, qx), __fmul_rn(qy, qy)),
                             __fmul_rn(qz, qz));
        g_query4[b * NQ] = make_float4(qx, qy, qz, sq);
    }
    __syncthreads();

    // ---- main FPS loop: one barrier per iteration ----
    for (int it = 1; it < NQ; ++it) {
        // warp-level skip
        float wdx = fmaxf(fmaxf(wlox - qx, qx - whix), 0.0f);
        float wdy = fmaxf(fmaxf(wloy - qy, qy - whiy), 0.0f);
        float wdz = fmaxf(fmaxf(wloz - qz, qz - whiz), 0.0f);
        float wlb2 = wdx * wdx + wdy * wdy + wdz * wdz;
        if (wlb2 * 0.999f < __uint_as_float(wd)) {
            // thread-level skip
            float dx = fmaxf(fmaxf(lox - qx, qx - hix), 0.0f);
            float dy = fmaxf(fmaxf(loy - qy, qy - hiy), 0.0f);
            float dz = fmaxf(fmaxf(loz - qz, qz - hiz), 0.0f);
            float lb2 = dx * dx + dy * dy + dz * dz;
            if (lb2 * 0.999f < bm) {
                // packed f32x2 rescan: 2 points per step, exact per-half RN
                unsigned long long nqx = pack2(-qx, -qx);
                unsigned long long nqy = pack2(-qy, -qy);
                unsigned long long nqz = pack2(-qz, -qz);
                float nbm = 0.0f;
#pragma unroll
                for (int j2 = 0; j2 < 8; ++j2) {
                    unsigned long long xv = sxq[j2 * 1024 + tid];
                    unsigned long long yv = syq[j2 * 1024 + tid];
                    unsigned long long zv = szq[j2 * 1024 + tid];
                    unsigned long long tx = add2(xv, nqx);   // x - qx (exact)
                    unsigned long long ty = add2(yv, nqy);
                    unsigned long long tz = add2(zv, nqz);
                    // plain non-contracted sum of squares, left-to-right
                    unsigned long long dd =
                        add2(add2(mul2(tx, tx), mul2(ty, ty)), mul2(tz, tz));
                    float dlo, dhi;
                    unpack2(dd, dlo, dhi);
                    float m0 = fminf(mind[2 * j2],     dlo);
                    float m1 = fminf(mind[2 * j2 + 1], dhi);
                    mind[2 * j2]     = m0;
                    mind[2 * j2 + 1] = m1;
                    nbm = fmaxf(nbm, fmaxf(m0, m1));
                }
                bm = nbm;
                // resolve winner payload (max inv among mind == bm)
                unsigned nb = 0;
#pragma unroll
                for (int j = 0; j < 16; ++j) {
                    if (mind[j] == bm) {
                        unsigned inv = (j & 1) ? (pk[j >> 1] >> 16)
                                               : (pk[j >> 1] & 0xFFFFu);
                        unsigned val = (inv << 16) |
                            (unsigned)((j >> 1) * 2048 + (tid << 1) + (j & 1));
                        nb = val > nb ? val : nb;
                    }
                }
                bpk = nb;
            }
            // stage 1: warp lexicographic argmax via redux (refresh cache)
            unsigned bd   = __float_as_uint(bm);
            unsigned dmax = __reduce_max_sync(0xffffffffu, bd);
            unsigned imax = __reduce_max_sync(0xffffffffu,
                                              (bd == dmax) ? bpk : 0u);
            wd = dmax; wi = imax;
        }
        const int p = it & 1;
        if (lane == 0)
            s_part[p][wid] = ((unsigned long long)wd << 32) | wi;
        __syncthreads();

        // stage 2: every warp reduces the 32 partials (no 2nd barrier)
        unsigned long long v = s_part[p][lane];
        unsigned d2 = (unsigned)(v >> 32);
        unsigned i2 = (unsigned)v;
        unsigned dW = __reduce_max_sync(0xffffffffu, d2);
        unsigned iW = __reduce_max_sync(0xffffffffu, (d2 == dW) ? i2 : 0u);
        unsigned slot = iW & 0xFFFFu;        // winner's float slot
        unsigned g    = 0xFFFFu ^ (iW >> 16);

        qx = sxf[slot]; qy = syf[slot]; qz = szf[slot];

        if (tid == 0) {
            out[OFF_IND + b * NQ + it] = (float)g;
            float* oq = out + OFF_Q + ((size_t)b * NQ + it) * 3;
            oq[0] = qx; oq[1] = qy; oq[2] = qz;
            float sq = __fadd_rn(__fadd_rn(__fmul_rn(qx, qx),
                                           __fmul_rn(qy, qy)),
                                 __fmul_rn(qz, qz));
            g_query4[b * NQ + it] = make_float4(qx, qy, qz, sq);
        }
    }
}

// ---------------------------------------------------------------------------
// Merged KNN (Gmid + Gout, one launch): warp-per-query exact top-(K+1),
// ascending (dist, idx) keys, float4 candidates with hoisted |p|^2.
// Distance matches reference pdist2: (sq_q+sq_p) - 2*dot (FMA dot),
// clamped >= 0 — identical op sequence, sq values precomputed with the
// same ops. Candidate buffer + running 21st-best threshold; flush
// selection uses redux min pairs.
// ---------------------------------------------------------------------------
__device__ __forceinline__ unsigned long long u64min(unsigned long long a,
                                                     unsigned long long b)
{ return a < b ? a : b; }

__device__ __forceinline__ void knn_flush(unsigned long long& cand,
                                          unsigned long long& curT,
                                          int& cnt,
                                          unsigned long long* buf,
                                          int lane)
{
    __syncwarp(0xffffffffu);
    unsigned long long r0 = cand;
    unsigned long long r1 = (lane      < cnt) ? buf[lane]      : ~0ULL;
    unsigned long long r2 = (lane + 32 < cnt) ? buf[lane + 32] : ~0ULL;
    unsigned long long r3 = (lane + 64 < cnt) ? buf[lane + 64] : ~0ULL;
    unsigned long long nc = ~0ULL;
#pragma unroll
    for (int r = 0; r < KK1; ++r) {
        unsigned long long m = u64min(u64min(r0, r1), u64min(r2, r3));
        unsigned md = (unsigned)(m >> 32), mi = (unsigned)m;
        unsigned dmin = __reduce_min_sync(0xffffffffu, md);
        unsigned imin = __reduce_min_sync(0xffffffffu,
                                          (md == dmin) ? mi : 0xFFFFFFFFu);
        unsigned long long w = ((unsigned long long)dmin << 32) | imin;
        if (lane == r) nc = w;
        if (r0 == w) r0 = ~0ULL;
        else if (r1 == w) r1 = ~0ULL;
        else if (r2 == w) r2 = ~0ULL;
        else if (r3 == w) r3 = ~0ULL;
    }
    cand = nc;
    curT = __shfl_sync(0xffffffffu, nc, KK1 - 1);
    cnt  = 0;
    __syncwarp(0xffffffffu);
}

#define KNN_BLOCKS_MID ((NB * NQ) / 8)    // 512

__global__ __launch_bounds__(256)
void knn_kernel(float* __restrict__ outNbrM, float* __restrict__ outDM,
                float* __restrict__ outNbrO, float* __restrict__ outDO)
{
    __shared__ unsigned long long s_buf[8][96];
    const int warp = threadIdx.x >> 5;
    const int lane = threadIdx.x & 31;
    const int mode = (blockIdx.x < KNN_BLOCKS_MID) ? 0 : 1;
    const int blk  = mode ? (blockIdx.x - KNN_BLOCKS_MID) : blockIdx.x;
    const int wg   = blk * 8 + warp;             // 0..4095
    const int b    = wg >> 10;
    const int m    = wg & 1023;

    float4 q4 = __ldg(&g_query4[b * NQ + m]);
    float qx = q4.x, qy = q4.y, qz = q4.z, sqq = q4.w;

    const float4* Pb = (mode == 0) ? (g_pts4 + (size_t)b * NPT)
                                   : (g_query4 + b * NQ);
    const int npts  = (mode == 0) ? NPT : NQ;
    float* outNbr   = (mode == 0) ? outNbrM : outNbrO;
    float* outD     = (mode == 0) ? outDM   : outDO;

    unsigned long long cand = ~0ULL, curT = ~0ULL;
    int cnt = 0;
    unsigned long long* buf = s_buf[warp];
    const unsigned ltmask = (1u << lane) - 1u;

    const int steps = npts >> 5;
    for (int j = 0; j < steps; j += 2) {
        int i0 = (j << 5) + lane;
        int i1 = i0 + 32;
        float4 a = __ldg(&Pb[i0]);
        float4 c = __ldg(&Pb[i1]);

        float da = __fmaf_rn(qz, a.z, __fmaf_rn(qy, a.y, __fmul_rn(qx, a.x)));
        float d0 = fmaxf(__fsub_rn(__fadd_rn(sqq, a.w), __fmul_rn(2.0f, da)),
                         0.0f);
        float dc = __fmaf_rn(qz, c.z, __fmaf_rn(qy, c.y, __fmul_rn(qx, c.x)));
        float d1 = fmaxf(__fsub_rn(__fadd_rn(sqq, c.w), __fmul_rn(2.0f, dc)),
                         0.0f);

        unsigned long long k0 =
            ((unsigned long long)__float_as_uint(d0) << 32) | (unsigned)i0;
        unsigned long long k1 =
            ((unsigned long long)__float_as_uint(d1) << 32) | (unsigned)i1;

        bool in0 = k0 < curT;
        unsigned b0 = __ballot_sync(0xffffffffu, in0);
        if (in0) buf[cnt + __popc(b0 & ltmask)] = k0;
        cnt += __popc(b0);

        bool in1 = k1 < curT;
        unsigned b1 = __ballot_sync(0xffffffffu, in1);
        if (in1) buf[cnt + __popc(b1 & ltmask)] = k1;
        cnt += __popc(b1);

        if (cnt >= 32) knn_flush(cand, curT, cnt, buf, lane);
    }
    if (cnt > 0) knn_flush(cand, curT, cnt, buf, lane);

    if (lane >= 1 && lane < KK1) {
        unsigned idx = (unsigned)(cand & 0xFFFFFFFFu);
        size_t o = (size_t)wg * KK + (lane - 1);
        outNbr[o] = (float)idx;
        float4 ps = __ldg(&Pb[idx]);
        outD[o * 3 + 0] = qx - ps.x;
        outD[o * 3 + 1] = qy - ps.y;
        outD[o * 3 + 2] = qz - ps.z;
    }
}

extern "C" void kernel_launch(void* const* d_in, const int* in_sizes, int n_in,
                              void* d_out, int out_size)
{
    const float* points = (const float*)d_in[0];
    float* out = (float*)d_out;

    const int fps_smem = 3 * NPT * (int)sizeof(float)
                       + NCELL * (int)sizeof(unsigned);   // 212992 B
    cudaFuncSetAttribute(fps_kernel,
                         cudaFuncAttributeMaxDynamicSharedMemorySize,
                         fps_smem);

    pack_kernel<<<(NB * NPT) / 256, 256>>>(points);
    fps_kernel<<<NB, 1024, fps_smem>>>(points, out);
    knn_kernel<<<2 * KNN_BLOCKS_MID, 256>>>(out + OFF_NM, out + OFF_DM,
                                            out + OFF_NO, out + OFF_DO);
}

// round 13
// speedup vs baseline: 1.2427x; 1.2427x over previous
#include <cuda_runtime.h>

#define NB  4
#define NPT 16384
#define NQ  1024
#define KK  20
#define KK1 21
#define NCELL 4096

// output layout (all f32, concatenated in reference return order)
#define OFF_IND 0
#define OFF_Q   (NB*NQ)                   // 4096
#define OFF_NM  (OFF_Q  + NB*NQ*3)        // 16384
#define OFF_DM  (OFF_NM + NB*NQ*KK)       // 98304
#define OFF_NO  (OFF_DM + NB*NQ*KK*3)     // 344064
#define OFF_DO  (OFF_NO + NB*NQ*KK)       // 425984

__device__ float4   g_query4[NB*NQ];    // sampled queries (x,y,z,|q|^2)
__device__ float4   g_pts4[NB*NPT];     // packed points  (x,y,z,|p|^2)
__device__ unsigned g_sidx[NB*NPT];     // sorted-pos -> original index

// ---------------- packed f32x2 helpers (per-half IEEE RN, exact) ----------
__device__ __forceinline__ unsigned long long pack2(float a, float b)
{ unsigned long long r; asm("mov.b64 %0, {%1, %2};" : "=l"(r) : "f"(a), "f"(b)); return r; }
__device__ __forceinline__ void unpack2(unsigned long long v, float& a, float& b)
{ asm("mov.b64 {%0, %1}, %2;" : "=f"(a), "=f"(b) : "l"(v)); }
__device__ __forceinline__ unsigned long long add2(unsigned long long a, unsigned long long b)
{ unsigned long long r; asm("add.rn.f32x2 %0, %1, %2;" : "=l"(r) : "l"(a), "l"(b)); return r; }
__device__ __forceinline__ unsigned long long mul2(unsigned long long a, unsigned long long b)
{ unsigned long long r; asm("mul.rn.f32x2 %0, %1, %2;" : "=l"(r) : "l"(a), "l"(b)); return r; }

__device__ __forceinline__ unsigned morton4(unsigned cx, unsigned cy, unsigned cz)
{
    unsigned m = 0;
#pragma unroll
    for (int b = 0; b < 4; ++b)
        m |= (((cx >> b) & 1u) << (3 * b))
           | (((cy >> b) & 1u) << (3 * b + 1))
           | (((cz >> b) & 1u) << (3 * b + 2));
    return m;
}

__device__ __forceinline__ unsigned cellof(float x, float y, float z)
{
    unsigned cx = (unsigned)fminf(fmaxf((x + 4.0f) * 2.0f, 0.0f), 15.0f);
    unsigned cy = (unsigned)fminf(fmaxf((y + 4.0f) * 2.0f, 0.0f), 15.0f);
    unsigned cz = (unsigned)fminf(fmaxf((z + 4.0f) * 2.0f, 0.0f), 15.0f);
    return morton4(cx, cy, cz);
}

// ---------------------------------------------------------------------------
// pack points into float4 (x,y,z,|p|^2); sq uses the exact reference op
// sequence so every later use is bit-identical.
// ---------------------------------------------------------------------------
__global__ __launch_bounds__(256)
void pack_kernel(const float* __restrict__ pts)
{
    int i = blockIdx.x * 256 + threadIdx.x;      // 0 .. NB*NPT-1
    float x = pts[i * 3], y = pts[i * 3 + 1], z = pts[i * 3 + 2];
    float sq = __fadd_rn(__fadd_rn(__fmul_rn(x, x), __fmul_rn(y, y)),
                         __fmul_rn(z, z));
    g_pts4[i] = make_float4(x, y, z, sq);
}

// ---------------------------------------------------------------------------
// Bucketed FPS — EXACT R10 configuration (841us validated): 1024 threads x
// 16-pt buckets, thread-level bbox skip only, packed f32x2 rescan
// (per-half IEEE RN, bit-identical to the reference's non-contracted scalar
// form), winner payload (inv<<16 | float_slot), one barrier per iteration.
// Only change: queries are published as float4 with reference-exact |q|^2.
// Tie-break = reference argmax first index (max inv = 0xFFFF^idx).
// ---------------------------------------------------------------------------
__global__ __launch_bounds__(1024, 1)
void fps_kernel(const float* __restrict__ pts, float* __restrict__ out)
{
    extern __shared__ float sm[];
    float*    sxf  = sm;                       // pair layout, see scatter
    float*    syf  = sm + NPT;
    float*    szf  = sm + 2 * NPT;
    unsigned* hist = (unsigned*)(sm + 3 * NPT);   // 16KB, sort phase only
    const unsigned long long* sxq = (const unsigned long long*)sxf;
    const unsigned long long* syq = (const unsigned long long*)syf;
    const unsigned long long* szq = (const unsigned long long*)szf;

    __shared__ unsigned long long s_part[2][32];
    __shared__ unsigned s_wsum[32];

    const int b    = blockIdx.x;
    const int tid  = threadIdx.x;
    const int lane = tid & 31, wid = tid >> 5;
    const float* P = pts + (size_t)b * NPT * 3;
    unsigned* sidx = g_sidx + b * NPT;

    // ---- counting sort by Morton cell ----
#pragma unroll
    for (int k = 0; k < 4; ++k) hist[tid + k * 1024] = 0;
    __syncthreads();

#pragma unroll
    for (int k = 0; k < 16; ++k) {
        int i = tid + k * 1024;
        float x = P[i * 3], y = P[i * 3 + 1], z = P[i * 3 + 2];
        atomicAdd(&hist[cellof(x, y, z)], 1u);
    }
    __syncthreads();

    // exclusive scan of hist[4096] in place
    unsigned v0 = hist[4 * tid], v1 = hist[4 * tid + 1];
    unsigned v2 = hist[4 * tid + 2], v3 = hist[4 * tid + 3];
    unsigned s = v0 + v1 + v2 + v3;
    unsigned inc = s;
#pragma unroll
    for (int o = 1; o < 32; o <<= 1) {
        unsigned n = __shfl_up_sync(0xffffffffu, inc, o);
        if (lane >= o) inc += n;
    }
    if (lane == 31) s_wsum[wid] = inc;
    __syncthreads();
    if (tid < 32) {
        unsigned w = s_wsum[tid], wi = w;
#pragma unroll
        for (int o = 1; o < 32; o <<= 1) {
            unsigned n = __shfl_up_sync(0xffffffffu, wi, o);
            if (tid >= o) wi += n;
        }
        s_wsum[tid] = wi - w;   // exclusive warp base
    }
    __syncthreads();
    unsigned base = s_wsum[wid] + inc - s;
    hist[4 * tid]     = base;
    hist[4 * tid + 1] = base + v0;
    hist[4 * tid + 2] = base + v0 + v1;
    hist[4 * tid + 3] = base + v0 + v1 + v2;
    __syncthreads();

    // scatter: sorted pos p (bucket t=p>>4, j=p&15) -> pair-layout float slot
    //   fs = (j>>1)*2048 + (t<<1) + (j&1)   (conflict-free LDS.64 per warp)
#pragma unroll
    for (int k = 0; k < 16; ++k) {
        int i = tid + k * 1024;
        float x = P[i * 3], y = P[i * 3 + 1], z = P[i * 3 + 2];
        unsigned pos = atomicAdd(&hist[cellof(x, y, z)], 1u);
        int t = (int)(pos >> 4), j = (int)(pos & 15u);
        int fs = (j >> 1) * 2048 + (t << 1) + (j & 1);
        sxf[fs] = x; syf[fs] = y; szf[fs] = z;
        sidx[pos] = (unsigned)i;
    }
    __syncthreads();

    // ---- per-bucket state ----
    float    mind[16];
    unsigned pk[8];
    float lox = 1e30f, loy = 1e30f, loz = 1e30f;
    float hix = -1e30f, hiy = -1e30f, hiz = -1e30f;
#pragma unroll
    for (int j = 0; j < 16; ++j) {
        int fs = (j >> 1) * 2048 + (tid << 1) + (j & 1);
        float x = sxf[fs], y = syf[fs], z = szf[fs];
        lox = fminf(lox, x); hix = fmaxf(hix, x);
        loy = fminf(loy, y); hiy = fmaxf(hiy, y);
        loz = fminf(loz, z); hiz = fmaxf(hiz, z);
        mind[j] = 1e10f;
        unsigned inv = 0xFFFFu ^ sidx[16 * tid + j];
        if (j & 1) pk[j >> 1] |= inv << 16;
        else       pk[j >> 1]  = inv;
    }
    float bm = 1e10f;
    unsigned bpk = 0;
#pragma unroll
    for (int j = 0; j < 16; ++j) {
        unsigned inv = (j & 1) ? (pk[j >> 1] >> 16) : (pk[j >> 1] & 0xFFFFu);
        unsigned val = (inv << 16) |
            (unsigned)((j >> 1) * 2048 + (tid << 1) + (j & 1));
        bpk = val > bpk ? val : bpk;    // all mind equal -> max inv
    }

    // first sample = original index 0 (broadcast LDG)
    float qx = P[0], qy = P[1], qz = P[2];
    if (tid == 0) {
        out[OFF_IND + b * NQ] = 0.0f;
        float* oq = out + OFF_Q + (size_t)b * NQ * 3;
        oq[0] = qx; oq[1] = qy; oq[2] = qz;
        float sq = __fadd_rn(__fadd_rn(__fmul_rn(qx, qx), __fmul_rn(qy, qy)),
                             __fmul_rn(qz, qz));
        g_query4[b * NQ] = make_float4(qx, qy, qz, sq);
    }
    __syncthreads();

    // ---- main FPS loop: one barrier per iteration ----
    for (int it = 1; it < NQ; ++it) {
        float dx = fmaxf(fmaxf(lox - qx, qx - hix), 0.0f);
        float dy = fmaxf(fmaxf(loy - qy, qy - hiy), 0.0f);
        float dz = fmaxf(fmaxf(loz - qz, qz - hiz), 0.0f);
        float lb2 = dx * dx + dy * dy + dz * dz;
        if (lb2 * 0.999f < bm) {
            // packed f32x2 rescan: 2 points per step, exact per-half RN
            unsigned long long nqx = pack2(-qx, -qx);
            unsigned long long nqy = pack2(-qy, -qy);
            unsigned long long nqz = pack2(-qz, -qz);
            float nbm = 0.0f;
#pragma unroll
            for (int j2 = 0; j2 < 8; ++j2) {
                unsigned long long xv = sxq[j2 * 1024 + tid];
                unsigned long long yv = syq[j2 * 1024 + tid];
                unsigned long long zv = szq[j2 * 1024 + tid];
                unsigned long long tx = add2(xv, nqx);   // x - qx (exact)
                unsigned long long ty = add2(yv, nqy);
                unsigned long long tz = add2(zv, nqz);
                // plain non-contracted sum of squares, left-to-right
                unsigned long long dd =
                    add2(add2(mul2(tx, tx), mul2(ty, ty)), mul2(tz, tz));
                float dlo, dhi;
                unpack2(dd, dlo, dhi);
                float m0 = fminf(mind[2 * j2],     dlo);
                float m1 = fminf(mind[2 * j2 + 1], dhi);
                mind[2 * j2]     = m0;
                mind[2 * j2 + 1] = m1;
                nbm = fmaxf(nbm, fmaxf(m0, m1));
            }
            bm = nbm;
            // resolve winner payload (max inv among mind == bm)
            unsigned nb = 0;
#pragma unroll
            for (int j = 0; j < 16; ++j) {
                if (mind[j] == bm) {
                    unsigned inv = (j & 1) ? (pk[j >> 1] >> 16)
                                           : (pk[j >> 1] & 0xFFFFu);
                    unsigned val = (inv << 16) |
                        (unsigned)((j >> 1) * 2048 + (tid << 1) + (j & 1));
                    nb = val > nb ? val : nb;
                }
            }
            bpk = nb;
        }

        // stage 1: warp lexicographic argmax via redux
        unsigned bd   = __float_as_uint(bm);
        unsigned dmax = __reduce_max_sync(0xffffffffu, bd);
        unsigned imax = __reduce_max_sync(0xffffffffu, (bd == dmax) ? bpk : 0u);
        const int p = it & 1;
        if (lane == 0)
            s_part[p][wid] = ((unsigned long long)dmax << 32) | imax;
        __syncthreads();

        // stage 2: every warp reduces the 32 partials (no 2nd barrier)
        unsigned long long v = s_part[p][lane];
        unsigned d2 = (unsigned)(v >> 32);
        unsigned i2 = (unsigned)v;
        unsigned dW = __reduce_max_sync(0xffffffffu, d2);
        unsigned iW = __reduce_max_sync(0xffffffffu, (d2 == dW) ? i2 : 0u);
        unsigned slot = iW & 0xFFFFu;        // winner's float slot
        unsigned g    = 0xFFFFu ^ (iW >> 16);

        qx = sxf[slot]; qy = syf[slot]; qz = szf[slot];

        if (tid == 0) {
            out[OFF_IND + b * NQ + it] = (float)g;
            float* oq = out + OFF_Q + ((size_t)b * NQ + it) * 3;
            oq[0] = qx; oq[1] = qy; oq[2] = qz;
            float sq = __fadd_rn(__fadd_rn(__fmul_rn(qx, qx),
                                           __fmul_rn(qy, qy)),
                                 __fmul_rn(qz, qz));
            g_query4[b * NQ + it] = make_float4(qx, qy, qz, sq);
        }
    }
}

// ---------------------------------------------------------------------------
// Merged KNN (Gmid + Gout, one launch): warp-per-query exact top-(K+1),
// ascending (dist, idx) keys, float4 candidates with hoisted |p|^2.
// Distance matches reference pdist2: (sq_q+sq_p) - 2*dot (FMA dot),
// clamped >= 0 — identical op sequence, sq precomputed with the same ops.
// Candidate buffer + running 21st-best threshold; flush uses redux pairs.
// ---------------------------------------------------------------------------
__device__ __forceinline__ unsigned long long u64min(unsigned long long a,
                                                     unsigned long long b)
{ return a < b ? a : b; }

__device__ __forceinline__ void knn_flush(unsigned long long& cand,
                                          unsigned long long& curT,
                                          int& cnt,
                                          unsigned long long* buf,
                                          int lane)
{
    __syncwarp(0xffffffffu);
    unsigned long long r0 = cand;
    unsigned long long r1 = (lane      < cnt) ? buf[lane]      : ~0ULL;
    unsigned long long r2 = (lane + 32 < cnt) ? buf[lane + 32] : ~0ULL;
    unsigned long long r3 = (lane + 64 < cnt) ? buf[lane + 64] : ~0ULL;
    unsigned long long nc = ~0ULL;
#pragma unroll
    for (int r = 0; r < KK1; ++r) {
        unsigned long long m = u64min(u64min(r0, r1), u64min(r2, r3));
        unsigned md = (unsigned)(m >> 32), mi = (unsigned)m;
        unsigned dmin = __reduce_min_sync(0xffffffffu, md);
        unsigned imin = __reduce_min_sync(0xffffffffu,
                                          (md == dmin) ? mi : 0xFFFFFFFFu);
        unsigned long long w = ((unsigned long long)dmin << 32) | imin;
        if (lane == r) nc = w;
        if (r0 == w) r0 = ~0ULL;
        else if (r1 == w) r1 = ~0ULL;
        else if (r2 == w) r2 = ~0ULL;
        else if (r3 == w) r3 = ~0ULL;
    }
    cand = nc;
    curT = __shfl_sync(0xffffffffu, nc, KK1 - 1);
    cnt  = 0;
    __syncwarp(0xffffffffu);
}

#define KNN_BLOCKS_MID ((NB * NQ) / 8)    // 512

__global__ __launch_bounds__(256)
void knn_kernel(float* __restrict__ outNbrM, float* __restrict__ outDM,
                float* __restrict__ outNbrO, float* __restrict__ outDO)
{
    __shared__ unsigned long long s_buf[8][96];
    const int warp = threadIdx.x >> 5;
    const int lane = threadIdx.x & 31;
    const int mode = (blockIdx.x < KNN_BLOCKS_MID) ? 0 : 1;
    const int blk  = mode ? (blockIdx.x - KNN_BLOCKS_MID) : blockIdx.x;
    const int wg   = blk * 8 + warp;             // 0..4095
    const int b    = wg >> 10;
    const int m    = wg & 1023;

    float4 q4 = __ldg(&g_query4[b * NQ + m]);
    float qx = q4.x, qy = q4.y, qz = q4.z, sqq = q4.w;

    const float4* Pb = (mode == 0) ? (g_pts4 + (size_t)b * NPT)
                                   : (g_query4 + b * NQ);
    const int npts  = (mode == 0) ? NPT : NQ;
    float* outNbr   = (mode == 0) ? outNbrM : outNbrO;
    float* outD     = (mode == 0) ? outDM   : outDO;

    unsigned long long cand = ~0ULL, curT = ~0ULL;
    int cnt = 0;
    unsigned long long* buf = s_buf[warp];
    const unsigned ltmask = (1u << lane) - 1u;

    const int steps = npts >> 5;
    for (int j = 0; j < steps; j += 2) {
        int i0 = (j << 5) + lane;
        int i1 = i0 + 32;
        float4 a = __ldg(&Pb[i0]);
        float4 c = __ldg(&Pb[i1]);

        float da = __fmaf_rn(qz, a.z, __fmaf_rn(qy, a.y, __fmul_rn(qx, a.x)));
        float d0 = fmaxf(__fsub_rn(__fadd_rn(sqq, a.w), __fmul_rn(2.0f, da)),
                         0.0f);
        float dc = __fmaf_rn(qz, c.z, __fmaf_rn(qy, c.y, __fmul_rn(qx, c.x)));
        float d1 = fmaxf(__fsub_rn(__fadd_rn(sqq, c.w), __fmul_rn(2.0f, dc)),
                         0.0f);

        unsigned long long k0 =
            ((unsigned long long)__float_as_uint(d0) << 32) | (unsigned)i0;
        unsigned long long k1 =
            ((unsigned long long)__float_as_uint(d1) << 32) | (unsigned)i1;

        bool in0 = k0 < curT;
        unsigned b0 = __ballot_sync(0xffffffffu, in0);
        if (in0) buf[cnt + __popc(b0 & ltmask)] = k0;
        cnt += __popc(b0);

        bool in1 = k1 < curT;
        unsigned b1 = __ballot_sync(0xffffffffu, in1);
        if (in1) buf[cnt + __popc(b1 & ltmask)] = k1;
        cnt += __popc(b1);

        if (cnt >= 32) knn_flush(cand, curT, cnt, buf, lane);
    }
    if (cnt > 0) knn_flush(cand, curT, cnt, buf, lane);

    if (lane >= 1 && lane < KK1) {
        unsigned idx = (unsigned)(cand & 0xFFFFFFFFu);
        size_t o = (size_t)wg * KK + (lane - 1);
        outNbr[o] = (float)idx;
        float4 ps = __ldg(&Pb[idx]);
        outD[o * 3 + 0] = qx - ps.x;
        outD[o * 3 + 1] = qy - ps.y;
        outD[o * 3 + 2] = qz - ps.z;
    }
}

extern "C" void kernel_launch(void* const* d_in, const int* in_sizes, int n_in,
                              void* d_out, int out_size)
{
    const float* points = (const float*)d_in[0];
    float* out = (float*)d_out;

    const int fps_smem = 3 * NPT * (int)sizeof(float)
                       + NCELL * (int)sizeof(unsigned);   // 212992 B
    cudaFuncSetAttribute(fps_kernel,
                         cudaFuncAttributeMaxDynamicSharedMemorySize,
                         fps_smem);

    pack_kernel<<<(NB * NPT) / 256, 256>>>(points);
    fps_kernel<<<NB, 1024, fps_smem>>>(points, out);
    knn_kernel<<<2 * KNN_BLOCKS_MID, 256>>>(out + OFF_NM, out + OFF_DM,
                                            out + OFF_NO, out + OFF_DO);
}

// round 14
// speedup vs baseline: 1.3518x; 1.0878x over previous
#include <cuda_runtime.h>

#define NB  4
#define NPT 16384
#define NQ  1024
#define KK  20
#define KK1 21
#define NCELL 4096
#define NBKT 1024          // 16-pt buckets per batch
#define SEED 256           // seed points for Gmid threshold

// output layout (all f32, concatenated in reference return order)
#define OFF_IND 0
#define OFF_Q   (NB*NQ)                   // 4096
#define OFF_NM  (OFF_Q  + NB*NQ*3)        // 16384
#define OFF_DM  (OFF_NM + NB*NQ*KK)       // 98304
#define OFF_NO  (OFF_DM + NB*NQ*KK*3)     // 344064
#define OFF_DO  (OFF_NO + NB*NQ*KK)       // 425984

__device__ float4   g_query4[NB*NQ];      // sampled queries (x,y,z,|q|^2)
__device__ float4   g_pts4[NB*NPT];       // packed points, orig order (x,y,z,|p|^2)
__device__ float4   g_pts4s[NB*NPT];      // sorted points (x,y,z, origidx bits)
__device__ float4   g_bbox[NB*NBKT*2];    // per-bucket bbox: lo, hi
__device__ int      g_cellstart[NB*NCELL];
__device__ unsigned g_sidx[NB*NPT];       // sorted-pos -> original index

// ---------------- packed f32x2 helpers (per-half IEEE RN, exact) ----------
__device__ __forceinline__ unsigned long long pack2(float a, float b)
{ unsigned long long r; asm("mov.b64 %0, {%1, %2};" : "=l"(r) : "f"(a), "f"(b)); return r; }
__device__ __forceinline__ void unpack2(unsigned long long v, float& a, float& b)
{ asm("mov.b64 {%0, %1}, %2;" : "=f"(a), "=f"(b) : "l"(v)); }
__device__ __forceinline__ unsigned long long add2(unsigned long long a, unsigned long long b)
{ unsigned long long r; asm("add.rn.f32x2 %0, %1, %2;" : "=l"(r) : "l"(a), "l"(b)); return r; }
__device__ __forceinline__ unsigned long long mul2(unsigned long long a, unsigned long long b)
{ unsigned long long r; asm("mul.rn.f32x2 %0, %1, %2;" : "=l"(r) : "l"(a), "l"(b)); return r; }

__device__ __forceinline__ unsigned morton4(unsigned cx, unsigned cy, unsigned cz)
{
    unsigned m = 0;
#pragma unroll
    for (int b = 0; b < 4; ++b)
        m |= (((cx >> b) & 1u) << (3 * b))
           | (((cy >> b) & 1u) << (3 * b + 1))
           | (((cz >> b) & 1u) << (3 * b + 2));
    return m;
}

__device__ __forceinline__ unsigned cellof(float x, float y, float z)
{
    unsigned cx = (unsigned)fminf(fmaxf((x + 4.0f) * 2.0f, 0.0f), 15.0f);
    unsigned cy = (unsigned)fminf(fmaxf((y + 4.0f) * 2.0f, 0.0f), 15.0f);
    unsigned cz = (unsigned)fminf(fmaxf((z + 4.0f) * 2.0f, 0.0f), 15.0f);
    return morton4(cx, cy, cz);
}

// ---------------------------------------------------------------------------
// pack points into float4 (x,y,z,|p|^2); sq uses the exact reference op
// sequence so every later use is bit-identical.
// ---------------------------------------------------------------------------
__global__ __launch_bounds__(256)
void pack_kernel(const float* __restrict__ pts)
{
    int i = blockIdx.x * 256 + threadIdx.x;      // 0 .. NB*NPT-1
    float x = pts[i * 3], y = pts[i * 3 + 1], z = pts[i * 3 + 2];
    float sq = __fadd_rn(__fadd_rn(__fmul_rn(x, x), __fmul_rn(y, y)),
                         __fmul_rn(z, z));
    g_pts4[i] = make_float4(x, y, z, sq);
}

// ---------------------------------------------------------------------------
// Bucketed FPS — EXACT 841us configuration; additions are off the critical
// path: exports sorted points (g_pts4s), bucket bboxes (g_bbox) and cell
// starts (g_cellstart) for the pruned Gmid KNN.
// ---------------------------------------------------------------------------
__global__ __launch_bounds__(1024, 1)
void fps_kernel(const float* __restrict__ pts, float* __restrict__ out)
{
    extern __shared__ float sm[];
    float*    sxf  = sm;                       // pair layout, see scatter
    float*    syf  = sm + NPT;
    float*    szf  = sm + 2 * NPT;
    unsigned* hist = (unsigned*)(sm + 3 * NPT);   // 16KB, sort phase only
    const unsigned long long* sxq = (const unsigned long long*)sxf;
    const unsigned long long* syq = (const unsigned long long*)syf;
    const unsigned long long* szq = (const unsigned long long*)szf;

    __shared__ unsigned long long s_part[2][32];
    __shared__ unsigned s_wsum[32];

    const int b    = blockIdx.x;
    const int tid  = threadIdx.x;
    const int lane = tid & 31, wid = tid >> 5;
    const float* P = pts + (size_t)b * NPT * 3;
    unsigned* sidx = g_sidx + b * NPT;

    // ---- counting sort by Morton cell ----
#pragma unroll
    for (int k = 0; k < 4; ++k) hist[tid + k * 1024] = 0;
    __syncthreads();

#pragma unroll
    for (int k = 0; k < 16; ++k) {
        int i = tid + k * 1024;
        float x = P[i * 3], y = P[i * 3 + 1], z = P[i * 3 + 2];
        atomicAdd(&hist[cellof(x, y, z)], 1u);
    }
    __syncthreads();

    // exclusive scan of hist[4096] in place
    unsigned v0 = hist[4 * tid], v1 = hist[4 * tid + 1];
    unsigned v2 = hist[4 * tid + 2], v3 = hist[4 * tid + 3];
    unsigned s = v0 + v1 + v2 + v3;
    unsigned inc = s;
#pragma unroll
    for (int o = 1; o < 32; o <<= 1) {
        unsigned n = __shfl_up_sync(0xffffffffu, inc, o);
        if (lane >= o) inc += n;
    }
    if (lane == 31) s_wsum[wid] = inc;
    __syncthreads();
    if (tid < 32) {
        unsigned w = s_wsum[tid], wi = w;
#pragma unroll
        for (int o = 1; o < 32; o <<= 1) {
            unsigned n = __shfl_up_sync(0xffffffffu, wi, o);
            if (tid >= o) wi += n;
        }
        s_wsum[tid] = wi - w;   // exclusive warp base
    }
    __syncthreads();
    unsigned base = s_wsum[wid] + inc - s;
    hist[4 * tid]     = base;
    hist[4 * tid + 1] = base + v0;
    hist[4 * tid + 2] = base + v0 + v1;
    hist[4 * tid + 3] = base + v0 + v1 + v2;
    // export cell starts for KNN seeding
    g_cellstart[b * NCELL + 4 * tid]     = (int)base;
    g_cellstart[b * NCELL + 4 * tid + 1] = (int)(base + v0);
    g_cellstart[b * NCELL + 4 * tid + 2] = (int)(base + v0 + v1);
    g_cellstart[b * NCELL + 4 * tid + 3] = (int)(base + v0 + v1 + v2);
    __syncthreads();

    // scatter: sorted pos p (bucket t=p>>4, j=p&15) -> pair-layout float slot
    //   fs = (j>>1)*2048 + (t<<1) + (j&1)   (conflict-free LDS.64 per warp)
    // also export sorted float4 with original-index payload
#pragma unroll
    for (int k = 0; k < 16; ++k) {
        int i = tid + k * 1024;
        float x = P[i * 3], y = P[i * 3 + 1], z = P[i * 3 + 2];
        unsigned pos = atomicAdd(&hist[cellof(x, y, z)], 1u);
        int t = (int)(pos >> 4), j = (int)(pos & 15u);
        int fs = (j >> 1) * 2048 + (t << 1) + (j & 1);
        sxf[fs] = x; syf[fs] = y; szf[fs] = z;
        sidx[pos] = (unsigned)i;
        g_pts4s[b * NPT + pos] = make_float4(x, y, z, __uint_as_float((unsigned)i));
    }
    __syncthreads();

    // ---- per-bucket state ----
    float    mind[16];
    unsigned pk[8];
    float lox = 1e30f, loy = 1e30f, loz = 1e30f;
    float hix = -1e30f, hiy = -1e30f, hiz = -1e30f;
#pragma unroll
    for (int j = 0; j < 16; ++j) {
        int fs = (j >> 1) * 2048 + (tid << 1) + (j & 1);
        float x = sxf[fs], y = syf[fs], z = szf[fs];
        lox = fminf(lox, x); hix = fmaxf(hix, x);
        loy = fminf(loy, y); hiy = fmaxf(hiy, y);
        loz = fminf(loz, z); hiz = fmaxf(hiz, z);
        mind[j] = 1e10f;
        unsigned inv = 0xFFFFu ^ sidx[16 * tid + j];
        if (j & 1) pk[j >> 1] |= inv << 16;
        else       pk[j >> 1]  = inv;
    }
    // export bucket bbox (bucket id == tid)
    g_bbox[(b * NBKT + tid) * 2]     = make_float4(lox, loy, loz, 0.0f);
    g_bbox[(b * NBKT + tid) * 2 + 1] = make_float4(hix, hiy, hiz, 0.0f);

    float bm = 1e10f;
    unsigned bpk = 0;
#pragma unroll
    for (int j = 0; j < 16; ++j) {
        unsigned inv = (j & 1) ? (pk[j >> 1] >> 16) : (pk[j >> 1] & 0xFFFFu);
        unsigned val = (inv << 16) |
            (unsigned)((j >> 1) * 2048 + (tid << 1) + (j & 1));
        bpk = val > bpk ? val : bpk;    // all mind equal -> max inv
    }

    // first sample = original index 0 (broadcast LDG)
    float qx = P[0], qy = P[1], qz = P[2];
    if (tid == 0) {
        out[OFF_IND + b * NQ] = 0.0f;
        float* oq = out + OFF_Q + (size_t)b * NQ * 3;
        oq[0] = qx; oq[1] = qy; oq[2] = qz;
        float sq = __fadd_rn(__fadd_rn(__fmul_rn(qx, qx), __fmul_rn(qy, qy)),
                             __fmul_rn(qz, qz));
        g_query4[b * NQ] = make_float4(qx, qy, qz, sq);
    }
    __syncthreads();

    // ---- main FPS loop: one barrier per iteration ----
    for (int it = 1; it < NQ; ++it) {
        float dx = fmaxf(fmaxf(lox - qx, qx - hix), 0.0f);
        float dy = fmaxf(fmaxf(loy - qy, qy - hiy), 0.0f);
        float dz = fmaxf(fmaxf(loz - qz, qz - hiz), 0.0f);
        float lb2 = dx * dx + dy * dy + dz * dz;
        if (lb2 * 0.999f < bm) {
            unsigned long long nqx = pack2(-qx, -qx);
            unsigned long long nqy = pack2(-qy, -qy);
            unsigned long long nqz = pack2(-qz, -qz);
            float nbm = 0.0f;
#pragma unroll
            for (int j2 = 0; j2 < 8; ++j2) {
                unsigned long long xv = sxq[j2 * 1024 + tid];
                unsigned long long yv = syq[j2 * 1024 + tid];
                unsigned long long zv = szq[j2 * 1024 + tid];
                unsigned long long tx = add2(xv, nqx);   // x - qx (exact)
                unsigned long long ty = add2(yv, nqy);
                unsigned long long tz = add2(zv, nqz);
                // plain non-contracted sum of squares, left-to-right
                unsigned long long dd =
                    add2(add2(mul2(tx, tx), mul2(ty, ty)), mul2(tz, tz));
                float dlo, dhi;
                unpack2(dd, dlo, dhi);
                float m0 = fminf(mind[2 * j2],     dlo);
                float m1 = fminf(mind[2 * j2 + 1], dhi);
                mind[2 * j2]     = m0;
                mind[2 * j2 + 1] = m1;
                nbm = fmaxf(nbm, fmaxf(m0, m1));
            }
            bm = nbm;
            unsigned nb = 0;
#pragma unroll
            for (int j = 0; j < 16; ++j) {
                if (mind[j] == bm) {
                    unsigned inv = (j & 1) ? (pk[j >> 1] >> 16)
                                           : (pk[j >> 1] & 0xFFFFu);
                    unsigned val = (inv << 16) |
                        (unsigned)((j >> 1) * 2048 + (tid << 1) + (j & 1));
                    nb = val > nb ? val : nb;
                }
            }
            bpk = nb;
        }

        unsigned bd   = __float_as_uint(bm);
        unsigned dmax = __reduce_max_sync(0xffffffffu, bd);
        unsigned imax = __reduce_max_sync(0xffffffffu, (bd == dmax) ? bpk : 0u);
        const int p = it & 1;
        if (lane == 0)
            s_part[p][wid] = ((unsigned long long)dmax << 32) | imax;
        __syncthreads();

        unsigned long long v = s_part[p][lane];
        unsigned d2 = (unsigned)(v >> 32);
        unsigned i2 = (unsigned)v;
        unsigned dW = __reduce_max_sync(0xffffffffu, d2);
        unsigned iW = __reduce_max_sync(0xffffffffu, (d2 == dW) ? i2 : 0u);
        unsigned slot = iW & 0xFFFFu;        // winner's float slot
        unsigned g    = 0xFFFFu ^ (iW >> 16);

        qx = sxf[slot]; qy = sxf[slot + NPT]; qz = sxf[slot + 2 * NPT];

        if (tid == 0) {
            out[OFF_IND + b * NQ + it] = (float)g;
            float* oq = out + OFF_Q + ((size_t)b * NQ + it) * 3;
            oq[0] = qx; oq[1] = qy; oq[2] = qz;
            float sq = __fadd_rn(__fadd_rn(__fmul_rn(qx, qx),
                                           __fmul_rn(qy, qy)),
                                 __fmul_rn(qz, qz));
            g_query4[b * NQ + it] = make_float4(qx, qy, qz, sq);
        }
    }
}

// ---------------------------------------------------------------------------
// KNN: warp-per-query exact top-(K+1), ascending (dist, idx) keys.
// Gmid (mode 0): bucket-pruned — seed 256 Morton-adjacent points for the
// threshold, then scan only buckets whose bbox lower bound can beat the
// current 21st key (skips provably exact). Gout (mode 1): brute over 1024.
// Distance matches reference pdist2: (sq_q+sq_p) - 2*dot (FMA dot),
// clamped >= 0, sq built with the identical op sequence.
// ---------------------------------------------------------------------------
__device__ __forceinline__ unsigned long long u64min(unsigned long long a,
                                                     unsigned long long b)
{ return a < b ? a : b; }

__device__ __forceinline__ void knn_flush(unsigned long long& cand,
                                          unsigned long long& curT,
                                          int& cnt,
                                          unsigned long long* buf,
                                          int lane)
{
    __syncwarp(0xffffffffu);
    unsigned long long r0 = cand;
    unsigned long long r1 = (lane      < cnt) ? buf[lane]      : ~0ULL;
    unsigned long long r2 = (lane + 32 < cnt) ? buf[lane + 32] : ~0ULL;
    unsigned long long r3 = (lane + 64 < cnt) ? buf[lane + 64] : ~0ULL;
    unsigned long long nc = ~0ULL;
#pragma unroll
    for (int r = 0; r < KK1; ++r) {
        unsigned long long m = u64min(u64min(r0, r1), u64min(r2, r3));
        unsigned md = (unsigned)(m >> 32), mi = (unsigned)m;
        unsigned dmin = __reduce_min_sync(0xffffffffu, md);
        unsigned imin = __reduce_min_sync(0xffffffffu,
                                          (md == dmin) ? mi : 0xFFFFFFFFu);
        unsigned long long w = ((unsigned long long)dmin << 32) | imin;
        if (lane == r) nc = w;
        if (r0 == w) r0 = ~0ULL;
        else if (r1 == w) r1 = ~0ULL;
        else if (r2 == w) r2 = ~0ULL;
        else if (r3 == w) r3 = ~0ULL;
    }
    cand = nc;
    curT = __shfl_sync(0xffffffffu, nc, KK1 - 1);
    cnt  = 0;
    __syncwarp(0xffffffffu);
}

#define KNN_BLOCKS_MID ((NB * NQ) / 8)    // 512

__global__ __launch_bounds__(256)
void knn_kernel(float* __restrict__ outNbrM, float* __restrict__ outDM,
                float* __restrict__ outNbrO, float* __restrict__ outDO)
{
    __shared__ unsigned long long s_buf[8][96];
    const int warp = threadIdx.x >> 5;
    const int lane = threadIdx.x & 31;
    const int mode = (blockIdx.x < KNN_BLOCKS_MID) ? 0 : 1;
    const int blk  = mode ? (blockIdx.x - KNN_BLOCKS_MID) : blockIdx.x;
    const int wg   = blk * 8 + warp;             // 0..4095
    const int b    = wg >> 10;
    const int m    = wg & 1023;

    float4 q4 = __ldg(&g_query4[b * NQ + m]);
    float qx = q4.x, qy = q4.y, qz = q4.z, sqq = q4.w;

    unsigned long long cand = ~0ULL, curT = ~0ULL;
    int cnt = 0;
    unsigned long long* buf = s_buf[warp];
    const unsigned ltmask = (1u << lane) - 1u;

    if (mode == 0) {
        // ---------------- pruned Gmid ----------------
        const float4* Ps = g_pts4s + (size_t)b * NPT;   // sorted, w=idx bits
        const float4* BB = g_bbox + (size_t)b * NBKT * 2;

        // seed window around the query's cell (bucket-aligned: 16 buckets)
        int cell = (int)cellof(qx, qy, qz);
        int cs = g_cellstart[b * NCELL + cell];
        int seedLo = cs - 128;
        if (seedLo < 0) seedLo = 0;
        if (seedLo > NPT - SEED) seedLo = NPT - SEED;
        seedLo &= ~31;
        const int seedHi = seedLo + SEED;

        for (int j = 0; j < SEED / 32; ++j) {
            int pos = seedLo + j * 32 + lane;
            float4 a = __ldg(&Ps[pos]);
            float sqp = __fadd_rn(__fadd_rn(__fmul_rn(a.x, a.x),
                                            __fmul_rn(a.y, a.y)),
                                  __fmul_rn(a.z, a.z));
            float dot = __fmaf_rn(qz, a.z,
                        __fmaf_rn(qy, a.y, __fmul_rn(qx, a.x)));
            float d = fmaxf(__fsub_rn(__fadd_rn(sqq, sqp),
                                      __fmul_rn(2.0f, dot)), 0.0f);
            unsigned long long key =
                ((unsigned long long)__float_as_uint(d) << 32) |
                __float_as_uint(a.w);
            bool ins = key < curT;
            unsigned bal = __ballot_sync(0xffffffffu, ins);
            if (ins) buf[cnt + __popc(bal & ltmask)] = key;
            cnt += __popc(bal);
            if (cnt >= 32) knn_flush(cand, curT, cnt, buf, lane);
        }
        if (cnt > 0) knn_flush(cand, curT, cnt, buf, lane);
        // curT is now a real 21-NN threshold (SEED=256 >= 21 candidates)

        // bucket pass: 32 lanes x 32 steps cover 1024 bboxes
        for (int s = 0; s < NBKT / 32; ++s) {
            int bkt = s * 32 + lane;
            float4 lo = __ldg(&BB[2 * bkt]);
            float4 hi = __ldg(&BB[2 * bkt + 1]);
            float ddx = fmaxf(fmaxf(lo.x - qx, qx - hi.x), 0.0f);
            float ddy = fmaxf(fmaxf(lo.y - qy, qy - hi.y), 0.0f);
            float ddz = fmaxf(fmaxf(lo.z - qz, qz - hi.z), 0.0f);
            float lb2 = ddx * ddx + ddy * ddy + ddz * ddz;
            float curTdf = __uint_as_float((unsigned)(curT >> 32));
            unsigned near = __ballot_sync(0xffffffffu,
                                          lb2 * 0.999f < curTdf);
            while (near) {
                int k = __ffs(near) - 1;
                near &= near - 1;
                float lbk = __shfl_sync(0xffffffffu, lb2, k);
                curTdf = __uint_as_float((unsigned)(curT >> 32));
                if (!(lbk * 0.999f < curTdf)) continue;   // re-test (tighter)
                int pos = (s * 32 + k) * 16 + lane;       // lanes 0..15
                unsigned long long key = ~0ULL;
                if (lane < 16 && !(pos >= seedLo && pos < seedHi)) {
                    float4 a = __ldg(&Ps[pos]);
                    float sqp = __fadd_rn(__fadd_rn(__fmul_rn(a.x, a.x),
                                                    __fmul_rn(a.y, a.y)),
                                          __fmul_rn(a.z, a.z));
                    float dot = __fmaf_rn(qz, a.z,
                                __fmaf_rn(qy, a.y, __fmul_rn(qx, a.x)));
                    float d = fmaxf(__fsub_rn(__fadd_rn(sqq, sqp),
                                              __fmul_rn(2.0f, dot)), 0.0f);
                    key = ((unsigned long long)__float_as_uint(d) << 32) |
                          __float_as_uint(a.w);
                }
                bool ins = key < curT;
                unsigned bal = __ballot_sync(0xffffffffu, ins);
                if (ins) buf[cnt + __popc(bal & ltmask)] = key;
                cnt += __popc(bal);
                if (cnt >= 64) knn_flush(cand, curT, cnt, buf, lane);
            }
        }
        if (cnt > 0) knn_flush(cand, curT, cnt, buf, lane);

        if (lane >= 1 && lane < KK1) {
            unsigned idx = (unsigned)(cand & 0xFFFFFFFFu);
            size_t o = (size_t)wg * KK + (lane - 1);
            outNbrM[o] = (float)idx;
            float4 ps = __ldg(&g_pts4[(size_t)b * NPT + idx]);
            outDM[o * 3 + 0] = qx - ps.x;
            outDM[o * 3 + 1] = qy - ps.y;
            outDM[o * 3 + 2] = qz - ps.z;
        }
    } else {
        // ---------------- brute Gout ----------------
        const float4* Pb = g_query4 + b * NQ;
        for (int j = 0; j < NQ / 32; j += 2) {
            int i0 = (j << 5) + lane;
            int i1 = i0 + 32;
            float4 a = __ldg(&Pb[i0]);
            float4 c = __ldg(&Pb[i1]);

            float da = __fmaf_rn(qz, a.z,
                       __fmaf_rn(qy, a.y, __fmul_rn(qx, a.x)));
            float d0 = fmaxf(__fsub_rn(__fadd_rn(sqq, a.w),
                                       __fmul_rn(2.0f, da)), 0.0f);
            float dc = __fmaf_rn(qz, c.z,
                       __fmaf_rn(qy, c.y, __fmul_rn(qx, c.x)));
            float d1 = fmaxf(__fsub_rn(__fadd_rn(sqq, c.w),
                                       __fmul_rn(2.0f, dc)), 0.0f);

            unsigned long long k0 =
                ((unsigned long long)__float_as_uint(d0) << 32) | (unsigned)i0;
            unsigned long long k1 =
                ((unsigned long long)__float_as_uint(d1) << 32) | (unsigned)i1;

            bool in0 = k0 < curT;
            unsigned b0 = __ballot_sync(0xffffffffu, in0);
            if (in0) buf[cnt + __popc(b0 & ltmask)] = k0;
            cnt += __popc(b0);

            bool in1 = k1 < curT;
            unsigned b1 = __ballot_sync(0xffffffffu, in1);
            if (in1) buf[cnt + __popc(b1 & ltmask)] = k1;
            cnt += __popc(b1);

            if (cnt >= 32) knn_flush(cand, curT, cnt, buf, lane);
        }
        if (cnt > 0) knn_flush(cand, curT, cnt, buf, lane);

        if (lane >= 1 && lane < KK1) {
            unsigned idx = (unsigned)(cand & 0xFFFFFFFFu);
            size_t o = (size_t)wg * KK + (lane - 1);
            outNbrO[o] = (float)idx;
            float4 ps = __ldg(&g_query4[b * NQ + idx]);
            outDO[o * 3 + 0] = qx - ps.x;
            outDO[o * 3 + 1] = qy - ps.y;
            outDO[o * 3 + 2] = qz - ps.z;
        }
    }
}

extern "C" void kernel_launch(void* const* d_in, const int* in_sizes, int n_in,
                              void* d_out, int out_size)
{
    const float* points = (const float*)d_in[0];
    float* out = (float*)d_out;

    const int fps_smem = 3 * NPT * (int)sizeof(float)
                       + NCELL * (int)sizeof(unsigned);   // 212992 B
    cudaFuncSetAttribute(fps_kernel,
                         cudaFuncAttributeMaxDynamicSharedMemorySize,
                         fps_smem);

    pack_kernel<<<(NB * NPT) / 256, 256>>>(points);
    fps_kernel<<<NB, 1024, fps_smem>>>(points, out);
    knn_kernel<<<2 * KNN_BLOCKS_MID, 256>>>(out + OFF_NM, out + OFF_DM,
                                            out + OFF_NO, out + OFF_DO);
}